// round 13
// baseline (speedup 1.0000x reference)
#include <cuda_runtime.h>
#include <math.h>

static constexpr int NG  = 512;
static constexpr int IMW = 256;
static constexpr int IMH = 256;
static constexpr int TW  = 16;   // tile width  (warp = 2 rows x 16 px)
static constexpr int TH  = 32;   // tile height (16 warps x 2 rows)
static constexpr int NTX = IMW / TW;   // 16
static constexpr int NTY = IMH / TH;   // 8
static constexpr float TANFOVX = 0.5f;
static constexpr float TANFOVY = 0.5f;
static constexpr float FXc = IMW / (2.0f * TANFOVX);
static constexpr float FYc = IMH / (2.0f * TANFOVY);
static constexpr float L2E = 1.4426950408889634f;   // log2(e)

__device__ __forceinline__ float ex2_approx(float x) {
    float r;
    asm("ex2.approx.ftz.f32 %0, %1;" : "=f"(r) : "f"(x));
    return r;
}

__global__ void __launch_bounds__(512) fused_raster_kernel(
    const float* __restrict__ means3D,
    const float* __restrict__ opac,
    const float* __restrict__ cols,
    const float* __restrict__ scales,
    const float* __restrict__ rots,
    const float* __restrict__ bg,
    const float* __restrict__ vm_g,
    const float* __restrict__ pm_g,
    float* __restrict__ out)
{
    // tile-compacted, depth-sorted per-gaussian params
    __shared__ float4 s_p0[NG];           // mx, my, -A/2*L2E, -B*L2E
    __shared__ float4 s_p1[NG];           // -C/2*L2E, op, z, cr
    __shared__ float2 s_p2[NG];           // cg, cb
    __shared__ float  s_z[NG + 4];        // sort keys (+4 pad for x4 unroll)
    __shared__ float  s_my[NG];
    __shared__ float  s_r2y[NG];          // exact y-marginal reach
    __shared__ unsigned short s_idx[16][NG];  // per-warp (2-row band) lists
    __shared__ float  vm[16], pm[16], s_bg[3];
    __shared__ int    s_wsum[16];

    const int tid = threadIdx.x;

    // ---- issue ALL global input loads up front ----
    const int g = tid;  // NG == blockDim.x
    float m0 = means3D[3*g+0], m1 = means3D[3*g+1], m2 = means3D[3*g+2];
    float4 q4 = ((const float4*)rots)[g];
    float sc0 = scales[3*g+0], sc1 = scales[3*g+1], sc2 = scales[3*g+2];
    float op  = opac[g];
    float cR  = cols[3*g+0], cG = cols[3*g+1], cB = cols[3*g+2];

    if (tid < 16) { vm[tid] = vm_g[tid]; pm[tid] = pm_g[tid]; }
    if (tid < 3)  { s_bg[tid] = bg[tid]; }
    __syncthreads();

    const int tilex = blockIdx.x & (NTX - 1);
    const int tiley = blockIdx.x >> 4;
    const float x0 = (float)(tilex * TW), y0 = (float)(tiley * TH);
    const float x1 = x0 + (TW - 1), y1 = y0 + (TH - 1);

    // ---- preprocess (1 gaussian/thread, ALL threads: parallel > minimal) ----
    float qr = q4.x, qx = q4.y, qy = q4.z, qz = q4.w;
    float qn = rsqrtf(qr*qr + qx*qx + qy*qy + qz*qz);
    qr *= qn; qx *= qn; qy *= qn; qz *= qn;
    float R[3][3] = {
        {1.f - 2.f*(qy*qy + qz*qz), 2.f*(qx*qy - qr*qz),       2.f*(qx*qz + qr*qy)},
        {2.f*(qx*qy + qr*qz),       1.f - 2.f*(qx*qx + qz*qz), 2.f*(qy*qz - qr*qx)},
        {2.f*(qx*qz - qr*qy),       2.f*(qy*qz + qr*qx),       1.f - 2.f*(qx*qx + qy*qy)}};

    float t0 = m0*vm[0] + m1*vm[4] + m2*vm[8]  + vm[12];
    float t1 = m0*vm[1] + m1*vm[5] + m2*vm[9]  + vm[13];
    float tz = m0*vm[2] + m1*vm[6] + m2*vm[10] + vm[14];
    float tzc = fmaxf(tz, 0.0001f);
    const float limx = 1.3f * TANFOVX, limy = 1.3f * TANFOVY;
    float it  = __fdividef(1.f, tzc);
    float txc = fminf(fmaxf(t0 * it, -limx), limx) * tzc;
    float tyc = fminf(fmaxf(t1 * it, -limy), limy) * tzc;
    float J00 = FXc * it, J02 = -FXc * txc * it * it;
    float J11 = FYc * it, J12 = -FYc * tyc * it * it;

    // T2 = J @ Wc (J has structural zeros)
    float T2r0[3], T2r1[3];
    #pragma unroll
    for (int k = 0; k < 3; k++) {
        T2r0[k] = J00*vm[k*4+0] + J02*vm[k*4+2];
        T2r1[k] = J11*vm[k*4+1] + J12*vm[k*4+2];
    }

    // V2 = (T2 @ R) * diag(s): cov = V2 V2^T  (skips forming Sigma)
    float V0[3], V1[3];
    #pragma unroll
    for (int c = 0; c < 3; c++) {
        float rc0 = R[0][c], rc1 = R[1][c], rc2 = R[2][c];
        V0[c] = T2r0[0]*rc0 + T2r0[1]*rc1 + T2r0[2]*rc2;
        V1[c] = T2r1[0]*rc0 + T2r1[1]*rc1 + T2r1[2]*rc2;
    }
    V0[0] *= sc0; V0[1] *= sc1; V0[2] *= sc2;
    V1[0] *= sc0; V1[1] *= sc1; V1[2] *= sc2;

    float c00 = V0[0]*V0[0] + V0[1]*V0[1] + V0[2]*V0[2] + 0.3f;
    float c01 = V0[0]*V1[0] + V0[1]*V1[1] + V0[2]*V1[2];
    float c11 = V1[0]*V1[0] + V1[1]*V1[1] + V1[2]*V1[2] + 0.3f;

    float det = c00*c11 - c01*c01;
    float det_inv = __fdividef(1.0f, det != 0.f ? det : 1.f);
    float Ai = c11 * det_inv;
    float Bi = -c01 * det_inv;
    float Ci = c00 * det_inv;
    bool vis = (det > 0.f) && (tz > 0.2f);

    // radii only where it's written (uniform branch, no barrier inside)
    if (blockIdx.x == 0) {
        float mid = 0.5f * (c00 + c11);
        float lam = mid + sqrtf(fmaxf(mid*mid - det, 0.1f));
        out[5 * IMH * IMW + g] = vis ? ceilf(3.0f * sqrtf(lam)) : 0.0f;
    }

    float p0h = m0*pm[0] + m1*pm[4] + m2*pm[8]  + pm[12];
    float p1h = m0*pm[1] + m1*pm[5] + m2*pm[9]  + pm[13];
    float p3h = m0*pm[3] + m1*pm[7] + m2*pm[11] + pm[15];
    float pw = __fdividef(1.0f, p3h + 1e-7f);
    float mx = ((p0h*pw + 1.0f) * IMW - 1.0f) * 0.5f;
    float my = ((p1h*pw + 1.0f) * IMH - 1.0f) * 0.5f;

    // exact marginal reach bounds (cull-only; fast log + safety margin keeps
    // them conservative): alpha>=1/255 needs dx^2<=2 c00 L && dy^2<=2 c11 L
    float r2x = -1.f, r2y = -1.f;
    if (vis && (op * 255.f > 1.f)) {
        float L = __logf(255.f * op) * 1.00002f + 1e-7f;
        r2x = 2.f * c00 * L;
        r2y = 2.f * c11 * L;
    } else {
        op = 0.f;
    }

    // tile overlap box test (conservative-exact vs the 1/255 cutoff)
    float cx = fminf(fmaxf(mx, x0), x1);
    float cy = fminf(fmaxf(my, y0), y1);
    float ddx = mx - cx, ddy = my - cy;
    bool keep = (r2x >= 0.f) && (ddx*ddx <= r2x) && (ddy*ddy <= r2y);

    unsigned bal = __ballot_sync(0xffffffffu, keep);
    const int lane = tid & 31, warp = tid >> 5;
    if (lane == 0) s_wsum[warp] = __popc(bal);
    __syncthreads();

    // distributed prefix: every thread computes its warp offset + total
    int woff = 0, count = 0;
    #pragma unroll
    for (int w = 0; w < 16; w++) {
        int v = s_wsum[w];
        woff  += (w < warp) ? v : 0;
        count += v;
    }

    if (keep) {
        int pos = woff + __popc(bal & ((1u << lane) - 1u));
        // conic constants pre-scaled by log2(e): composite uses raw ex2
        s_p0[pos] = make_float4(mx, my, -0.5f * Ai * L2E, -Bi * L2E);
        s_p1[pos] = make_float4(-0.5f * Ci * L2E, op, tz, cR);
        s_p2[pos] = make_float2(cG, cB);
        s_z[pos]  = tz;
        s_my[pos] = my;
        s_r2y[pos] = r2y;
    }
    if (tid < 4) s_z[count + tid] = 1e30f;   // pad for x4-unrolled scan
    __syncthreads();

    // ---- register-staged stable rank sort by depth (x4-unrolled scan) ----
    const bool active = (tid < count);
    float4 r0, r1;
    float2 r2v;
    float rmy = 0.f, rr2 = 0.f;
    int rank = 0;
    if (active) {
        r0  = s_p0[tid];
        r1  = s_p1[tid];
        r2v = s_p2[tid];
        rmy = s_my[tid];
        rr2 = s_r2y[tid];
        float zk = r1.z;
        for (int j = 0; j < count; j += 4) {
            float z0v = s_z[j+0], z1v = s_z[j+1], z2v = s_z[j+2], z3v = s_z[j+3];
            rank += (z0v < zk) || (z0v == zk && (j+0) < tid);
            rank += (z1v < zk) || (z1v == zk && (j+1) < tid);
            rank += (z2v < zk) || (z2v == zk && (j+2) < tid);
            rank += (z3v < zk) || (z3v == zk && (j+3) < tid);
        }
    }
    __syncthreads();
    if (active) {
        s_p0[rank] = r0; s_p1[rank] = r1; s_p2[rank] = r2v;
        s_my[rank] = rmy; s_r2y[rank] = rr2;
    }
    __syncthreads();

    // ---- per-warp band culling (warp = 2 rows x 16 px) ----
    const float pyb = y0 + (float)(warp * 2);   // band top row
    int wcount = 0;
    for (int base = 0; base < count; base += 32) {
        int k = base + lane;
        bool ok = false;
        if (k < count) {
            float dy0 = s_my[k] - pyb;
            float dy1 = dy0 - 1.f;
            float d2  = fminf(dy0 * dy0, dy1 * dy1);
            ok = (d2 <= s_r2y[k]);   // else alpha < 1/255 on both rows (exact)
        }
        unsigned b = __ballot_sync(0xffffffffu, ok);
        if (ok)
            s_idx[warp][wcount + __popc(b & ((1u << lane) - 1u))] = (unsigned short)k;
        wcount += __popc(b);
    }

    // ---- per-pixel front-to-back compositing (branchless, ex2-folded) ----
    const float px  = x0 + (float)(lane & 15);
    const float pyr = pyb + (float)(lane >> 4);

    float T = 1.f, cr = 0.f, cg = 0.f, cb = 0.f, dep = 0.f;
    #pragma unroll 8
    for (int i = 0; i < wcount; i++) {
        int k = (int)s_idx[warp][i];
        float4 q0 = s_p0[k];
        float4 q1 = s_p1[k];
        float2 q2 = s_p2[k];
        float dx = q0.x - px;
        float dy = q0.y - pyr;
        // power2 = log2(e) * (-A/2 dx^2 - B dx dy - C/2 dy^2); sign preserved
        float t  = fmaf(q0.z, dx, q0.w * dy);
        float power2 = fmaf(t, dx, (q1.x * dy) * dy);
        float a = fminf(0.99f, q1.y * ex2_approx(power2));
        a = ((power2 <= 0.f) && (a >= 1.f / 255.f)) ? a : 0.f;
        float w = a * T;
        cr  += w * q1.w;
        cg  += w * q2.x;
        cb  += w * q2.y;
        dep += w * q1.z;
        T   -= w;
    }

    const int pidx = (tiley * TH + warp * 2 + (lane >> 4)) * IMW
                   + tilex * TW + (lane & 15);
    const int HW = IMH * IMW;
    out[0*HW + pidx] = cr + T * s_bg[0];
    out[1*HW + pidx] = cg + T * s_bg[1];
    out[2*HW + pidx] = cb + T * s_bg[2];
    out[3*HW + pidx] = dep;
    out[4*HW + pidx] = T;
}

extern "C" void kernel_launch(void* const* d_in, const int* in_sizes, int n_in,
                              void* d_out, int out_size)
{
    const float* means3D = (const float*)d_in[0];
    const float* opac    = (const float*)d_in[1];
    const float* cols    = (const float*)d_in[2];
    const float* scales  = (const float*)d_in[3];
    const float* rots    = (const float*)d_in[4];
    const float* bg      = (const float*)d_in[5];
    const float* vm      = (const float*)d_in[6];
    const float* pm      = (const float*)d_in[7];
    float* out = (float*)d_out;

    fused_raster_kernel<<<NTX * NTY, 512>>>(means3D, opac, cols, scales, rots,
                                            bg, vm, pm, out);
}